// round 11
// baseline (speedup 1.0000x reference)
#include <cuda_runtime.h>
#include <cuda_bf16.h>
#include <stdint.h>
#include <math.h>

typedef unsigned int u32;
typedef unsigned long long u64;

// Problem constants
constexpr int B_   = 2;
constexpr int S_   = 2048;
constexpr int HID_ = 1024;
constexpr int NH_  = 16;
constexpr int DK_  = 64;
constexpr int M_   = B_ * S_;   // 4096

// ---------------------------------------------------------------------------
// Scratch (device globals; no allocation allowed)
// ---------------------------------------------------------------------------
__device__ float g_q  [B_ * NH_ * S_ * DK_];
__device__ float g_k  [B_ * NH_ * S_ * DK_];
__device__ float g_v  [B_ * NH_ * S_ * DK_];
__device__ float g_att[B_ * S_ * HID_];

// ---------------------------------------------------------------------------
// f32x2 packed helpers (FFMA2 path; PTX-only, sm_100+)
// ---------------------------------------------------------------------------
__device__ __forceinline__ void fma2(u64& d, u64 a, u64 b) {
    asm("fma.rn.f32x2 %0, %1, %2, %0;" : "+l"(d) : "l"(a), "l"(b));
}
__device__ __forceinline__ void mul2(u64& d, u64 a) {
    asm("mul.rn.f32x2 %0, %0, %1;" : "+l"(d) : "l"(a));
}
__device__ __forceinline__ u64 pk2(float lo, float hi) {
    u64 r;
    asm("mov.b64 %0, {%1, %2};" : "=l"(r)
        : "r"(__float_as_uint(lo)), "r"(__float_as_uint(hi)));
    return r;
}
__device__ __forceinline__ float2 upk2(u64 v) {
    u32 lo, hi;
    asm("mov.b64 {%0, %1}, %2;" : "=r"(lo), "=r"(hi) : "l"(v));
    return make_float2(__uint_as_float(lo), __uint_as_float(hi));
}

// ---------------------------------------------------------------------------
// SGEMM (f32x2, reduction-packed): C = A @ W^T + bias
// A [M,1024] row-major, W [N,1024] row-major. CTA tile 128m x 64n, k-tile 64.
// 256 threads: tx 0..15 (n, interleaved n = tx+16j), ty 0..15 (m = ty*8+i).
// MODE 0: C row-major [M,1024];  MODE 1: C in [B,NH,S,DK] layout.
// SCALEA: scale A rows by (1 + abias[row]) during staging (fuses K/V prep).
// ---------------------------------------------------------------------------
constexpr int GS_LD = 68;                               // smem row stride (floats)
constexpr int SGEMM_SMEM = (128 + 64) * GS_LD * 4;      // 52224 bytes

template <int MODE, int SCALEA>
__global__ __launch_bounds__(256)
void sgemm2(const float* __restrict__ A, const float* __restrict__ W,
            const float* __restrict__ bias, const float* __restrict__ abias,
            float* __restrict__ C) {
    extern __shared__ float smf[];
    float* As = smf;                    // [128][GS_LD]
    float* Ws = smf + 128 * GS_LD;      // [64][GS_LD]

    const int tid = threadIdx.x;
    const int tx  = tid & 15;
    const int ty  = tid >> 4;
    const int m0  = blockIdx.y * 128;
    const int n0  = blockIdx.x * 64;

    u64 acc2[8][4];
#pragma unroll
    for (int i = 0; i < 8; i++)
#pragma unroll
        for (int j = 0; j < 4; j++) acc2[i][j] = 0ull;

    for (int kt = 0; kt < 16; kt++) {
        const int k0 = kt * 64;
        __syncthreads();
#pragma unroll
        for (int it = 0; it < 8; it++) {
            int f = tid + it * 256;
            int r = f >> 4;
            int c = (f & 15) * 4;
            float4 a = *(const float4*)&A[(size_t)(m0 + r) * 1024 + k0 + c];
            if (SCALEA) {
                float fs = 1.0f + abias[m0 + r];
                a.x *= fs; a.y *= fs; a.z *= fs; a.w *= fs;
            }
            *(float4*)&As[r * GS_LD + c] = a;
        }
#pragma unroll
        for (int it = 0; it < 4; it++) {
            int f = tid + it * 256;
            int r = f >> 4;
            int c = (f & 15) * 4;
            *(float4*)&Ws[r * GS_LD + c] =
                *(const float4*)&W[(size_t)(n0 + r) * 1024 + k0 + c];
        }
        __syncthreads();

#pragma unroll 4
        for (int d4 = 0; d4 < 16; d4++) {
            ulonglong2 bv[4];
#pragma unroll
            for (int j = 0; j < 4; j++)
                bv[j] = *(const ulonglong2*)&Ws[(tx + 16 * j) * GS_LD + d4 * 4];
#pragma unroll
            for (int i = 0; i < 8; i++) {
                ulonglong2 av = *(const ulonglong2*)&As[(ty * 8 + i) * GS_LD + d4 * 4];
#pragma unroll
                for (int j = 0; j < 4; j++) {
                    fma2(acc2[i][j], av.x, bv[j].x);
                    fma2(acc2[i][j], av.y, bv[j].y);
                }
            }
        }
    }

    // epilogue: horizontal add of packed halves, + bias, store
#pragma unroll
    for (int i = 0; i < 8; i++) {
        const int m = m0 + ty * 8 + i;
        const int bb = m >> 11;
        const int ss = m & (S_ - 1);
#pragma unroll
        for (int j = 0; j < 4; j++) {
            const int n = n0 + tx + 16 * j;
            float2 p = upk2(acc2[i][j]);
            float val = p.x + p.y + bias[n];
            if (MODE == 0) {
                C[(size_t)m * 1024 + n] = val;
            } else {
                const int h = n >> 6;
                const int d = n & 63;
                C[((size_t)(bb * NH_ + h) * S_ + ss) * DK_ + d] = val;
            }
        }
    }
}

// ---------------------------------------------------------------------------
// Fused flash attention (f32x2): per (b,h), 64 q-rows per CTA, online softmax.
// grid (S/64, NH, B), 256 threads (tx 0..15, ty 0..15).
// GEMM1: reduction-packed over d (Q,K row-major in smem).
// PV:    packed over q-pairs, V d-duplicated + bank-interleaved.
// smem floats:
//   Qs  [64][68] @0        Ks  [64][68] @4352   Vs2 [64][128] @8704
//   ST  [64][68] @16896    alf[64] @21248  linv[64] @21312  msk[64] @21376
// ---------------------------------------------------------------------------
constexpr int FL_LD = 68;
constexpr int FLASH_SMEM = 21440 * 4;    // 85760 bytes

__global__ __launch_bounds__(256)
void flash_kernel(const float* __restrict__ Q, const float* __restrict__ K,
                  const float* __restrict__ V, const int* __restrict__ mask,
                  float* __restrict__ out) {
    extern __shared__ float sm[];
    float* Qs   = sm;            // [q][d] stride 68
    float* Ks   = sm + 4352;     // [k][d] stride 68
    float* Vs2  = sm + 8704;     // [k][2d] stride 128 (dup)
    float* ST   = sm + 16896;    // [k][q] stride 68
    float* alf  = sm + 21248;
    float* linv = sm + 21312;
    int*   msk  = (int*)(sm + 21376);

    const int tid = threadIdx.x;
    const int tx  = tid & 15;
    const int ty  = tid >> 4;
    const int b   = blockIdx.z;
    const int h   = blockIdx.y;
    const int q0  = blockIdx.x * 64;
    const int bh  = b * NH_ + h;

    const float* Qb = Q + (size_t)bh * S_ * DK_;
    const float* Kb = K + (size_t)bh * S_ * DK_;
    const float* Vb = V + (size_t)bh * S_ * DK_;
    const int*   mb = mask + b * S_;

    // load Q tile row-major [q][d]
#pragma unroll
    for (int it = 0; it < 4; it++) {
        int f = tid + it * 256;
        int r = f >> 4;
        int c = (f & 15) * 4;
        *(float4*)&Qs[r * FL_LD + c] =
            *(const float4*)&Qb[(size_t)(q0 + r) * DK_ + c];
    }

    u64 Ob2[2][4];
#pragma unroll
    for (int ip = 0; ip < 2; ip++)
#pragma unroll
        for (int j = 0; j < 4; j++) Ob2[ip][j] = 0ull;

    const int r   = ty * 4 + (tx & 3);   // row this thread scans
    const int k0s = (tx >> 2) * 16;      // k segment for the scan
    float m_row = -1.0e30f;
    float l_row = 0.0f;

    for (int kt = 0; kt < S_; kt += 64) {
        __syncthreads();   // prev PV done before we overwrite Ks/Vs2/ST

        // stage K [k][d] and V duplicated [k][2d]
#pragma unroll
        for (int it = 0; it < 4; it++) {
            int f = tid + it * 256;
            int rr = f >> 4;
            int cc = (f & 15) * 4;
            *(float4*)&Ks[rr * FL_LD + cc] =
                *(const float4*)&Kb[(size_t)(kt + rr) * DK_ + cc];
            float4 vv = *(const float4*)&Vb[(size_t)(kt + rr) * DK_ + cc];
            *(float2*)&Vs2[rr * 128 + 2 * (cc + 0)] = make_float2(vv.x, vv.x);
            *(float2*)&Vs2[rr * 128 + 2 * (cc + 1)] = make_float2(vv.y, vv.y);
            *(float2*)&Vs2[rr * 128 + 2 * (cc + 2)] = make_float2(vv.z, vv.z);
            *(float2*)&Vs2[rr * 128 + 2 * (cc + 3)] = make_float2(vv.w, vv.w);
        }
        if (tid < 64) msk[tid] = mb[kt + tid];
        __syncthreads();

        // GEMM1: S[q][k] reduction-packed over d. q = ty*4+i, k = tx+16j.
        u64 sacc2[4][4];
#pragma unroll
        for (int i = 0; i < 4; i++)
#pragma unroll
            for (int j = 0; j < 4; j++) sacc2[i][j] = 0ull;

#pragma unroll 4
        for (int d4 = 0; d4 < 16; d4++) {
            ulonglong2 bv[4];
#pragma unroll
            for (int j = 0; j < 4; j++)
                bv[j] = *(const ulonglong2*)&Ks[(tx + 16 * j) * FL_LD + d4 * 4];
#pragma unroll
            for (int i = 0; i < 4; i++) {
                ulonglong2 av = *(const ulonglong2*)&Qs[(ty * 4 + i) * FL_LD + d4 * 4];
#pragma unroll
                for (int j = 0; j < 4; j++) {
                    fma2(sacc2[i][j], av.x, bv[j].x);
                    fma2(sacc2[i][j], av.y, bv[j].y);
                }
            }
        }

        // horizontal add, mask+scale, store transposed ST[k][q]
#pragma unroll
        for (int j = 0; j < 4; j++) {
            const int kk = tx + 16 * j;
            const int mk = msk[kk];
#pragma unroll
            for (int i = 0; i < 4; i++) {
                float2 p = upk2(sacc2[i][j]);
                ST[kk * FL_LD + ty * 4 + i] =
                    mk ? (p.x + p.y) * 0.125f : -10000.0f;
            }
        }
        __syncthreads();

        // online softmax row update (4 threads per row, 16 k each)
        float tm = -1.0e30f;
#pragma unroll
        for (int t = 0; t < 16; t++)
            tm = fmaxf(tm, ST[(k0s + t) * FL_LD + r]);
        tm = fmaxf(tm, __shfl_xor_sync(0xFFFFFFFFu, tm, 4));
        tm = fmaxf(tm, __shfl_xor_sync(0xFFFFFFFFu, tm, 8));

        const float m_new = fmaxf(m_row, tm);
        const float al    = __expf(m_row - m_new);
        float sum = 0.0f;
#pragma unroll
        for (int t = 0; t < 16; t++) {
            float e = __expf(ST[(k0s + t) * FL_LD + r] - m_new);
            ST[(k0s + t) * FL_LD + r] = e;
            sum += e;
        }
        sum += __shfl_xor_sync(0xFFFFFFFFu, sum, 4);
        sum += __shfl_xor_sync(0xFFFFFFFFu, sum, 8);
        l_row = l_row * al + sum;
        m_row = m_new;
        if ((tx >> 2) == 0) alf[r] = al;
        __syncthreads();

        // rescale O (packed) and accumulate P @ V
        {
            u64 al2_0 = pk2(alf[ty * 4 + 0], alf[ty * 4 + 1]);
            u64 al2_1 = pk2(alf[ty * 4 + 2], alf[ty * 4 + 3]);
#pragma unroll
            for (int j = 0; j < 4; j++) {
                mul2(Ob2[0][j], al2_0);
                mul2(Ob2[1][j], al2_1);
            }
        }

#pragma unroll 8
        for (int kk = 0; kk < 64; kk++) {
            u64 p2_0 = *(const u64*)&ST[kk * FL_LD + ty * 4 + 0];
            u64 p2_1 = *(const u64*)&ST[kk * FL_LD + ty * 4 + 2];
            u64 v2[4];
#pragma unroll
            for (int j = 0; j < 4; j++)
                v2[j] = *(const u64*)&Vs2[kk * 128 + 2 * (tx + 16 * j)];
#pragma unroll
            for (int j = 0; j < 4; j++) {
                fma2(Ob2[0][j], p2_0, v2[j]);
                fma2(Ob2[1][j], p2_1, v2[j]);
            }
        }
    }

    if ((tx >> 2) == 0) linv[r] = 1.0f / l_row;
    __syncthreads();

    // normalize and write to [B,S,HID]; d = tx + 16j (coalesced over tx)
#pragma unroll
    for (int ip = 0; ip < 2; ip++) {
        const int qa = ty * 4 + 2 * ip;
        const float rv0 = linv[qa];
        const float rv1 = linv[qa + 1];
#pragma unroll
        for (int j = 0; j < 4; j++) {
            float2 p = upk2(Ob2[ip][j]);
            const int d = tx + 16 * j;
            out[((size_t)b * S_ + q0 + qa)     * HID_ + h * DK_ + d] = p.x * rv0;
            out[((size_t)b * S_ + q0 + qa + 1) * HID_ + h * DK_ + d] = p.y * rv1;
        }
    }
}

// ---------------------------------------------------------------------------
// launch
// ---------------------------------------------------------------------------
extern "C" void kernel_launch(void* const* d_in, const int* in_sizes, int n_in,
                              void* d_out, int out_size) {
    const float* query = (const float*)d_in[0];
    const float* key   = (const float*)d_in[1];
    const float* value = (const float*)d_in[2];
    const float* bias  = (const float*)d_in[3];
    const int*   mask  = (const int*)  d_in[4];
    const float* wq    = (const float*)d_in[5];
    const float* bq    = (const float*)d_in[6];
    const float* wk    = (const float*)d_in[7];
    const float* bk    = (const float*)d_in[8];
    const float* wv    = (const float*)d_in[9];
    const float* bv    = (const float*)d_in[10];
    const float* wo    = (const float*)d_in[11];
    const float* bo    = (const float*)d_in[12];
    float* out = (float*)d_out;

    float *p_q, *p_k, *p_v, *p_att;
    cudaGetSymbolAddress((void**)&p_q,   g_q);
    cudaGetSymbolAddress((void**)&p_k,   g_k);
    cudaGetSymbolAddress((void**)&p_v,   g_v);
    cudaGetSymbolAddress((void**)&p_att, g_att);

    cudaFuncSetAttribute(sgemm2<0, 0>, cudaFuncAttributeMaxDynamicSharedMemorySize, SGEMM_SMEM);
    cudaFuncSetAttribute(sgemm2<1, 0>, cudaFuncAttributeMaxDynamicSharedMemorySize, SGEMM_SMEM);
    cudaFuncSetAttribute(sgemm2<1, 1>, cudaFuncAttributeMaxDynamicSharedMemorySize, SGEMM_SMEM);
    cudaFuncSetAttribute(flash_kernel, cudaFuncAttributeMaxDynamicSharedMemorySize, FLASH_SMEM);

    dim3 ggrid(1024 / 64, M_ / 128);    // (16, 32)

    // 1) projections (K/V scaled by 1+bias during staging), write [B,NH,S,DK]
    sgemm2<1, 0><<<ggrid, 256, SGEMM_SMEM>>>(query, wq, bq, nullptr, p_q);
    sgemm2<1, 1><<<ggrid, 256, SGEMM_SMEM>>>(key,   wk, bk, bias,    p_k);
    sgemm2<1, 1><<<ggrid, 256, SGEMM_SMEM>>>(value, wv, bv, bias,    p_v);

    // 2) fused flash attention
    {
        dim3 grid(S_ / 64, NH_, B_);    // (32, 16, 2)
        flash_kernel<<<grid, 256, FLASH_SMEM>>>(p_q, p_k, p_v, mask, p_att);
    }

    // 3) output projection (row-major out)
    sgemm2<0, 0><<<ggrid, 256, SGEMM_SMEM>>>(p_att, wo, bo, nullptr, out);
}